// round 6
// baseline (speedup 1.0000x reference)
#include <cuda_runtime.h>
#include <cuda_bf16.h>
#include <cstddef>
#include <cstdint>

// SparseConv: out[out_map[k,m]] += x[in_map[k,m]] @ W[k]   (K=27, M=65536, Cin=Cout=64)
//
// Round 6: warp-level bf16 mma.sync, 3-term hi/lo split.
//   - B-hi fragments in registers, B-lo LDSM hoisted (loaded once per (s,p))
//   - 296 CTAs (exactly 2/SM), flattened balanced work split, W restaged on k-change
//   - triple-buffered smem index staging, 2 tiles ahead (kills dependent-LDG chains)
//   - double-buffered A with software-pipelined gather

#define CIN     64
#define COUT    64
#define EDGES   128
#define THREADS 256
#define NCTAS   296

#define STRIDE_A 144
#define STRIDE_B 144

#define ABUF     (EDGES * STRIDE_A)             // 18432 B per (buf, hi/lo) plane
#define SM_B_HI  (4 * ABUF)                     // 73728
#define SM_B_LO  (SM_B_HI + CIN * STRIDE_B)     // 82944
#define SM_IDX   (SM_B_LO + CIN * STRIDE_B)     // 92160 (3 slots x 256 ints)
#define SM_TOTAL (SM_IDX + 3 * 256 * 4)         // 95232 B -> 2 CTAs/SM

__device__ __forceinline__ uint32_t smem_u32(const void* p) {
    uint32_t a;
    asm("{ .reg .u64 t; cvta.to.shared.u64 t, %1; cvt.u32.u64 %0, t; }" : "=r"(a) : "l"(p));
    return a;
}
__device__ __forceinline__ uint32_t pack_bf16x2(float hi_elem, float lo_elem) {
    uint32_t r;
    asm("cvt.rn.bf16x2.f32 %0, %1, %2;" : "=r"(r) : "f"(hi_elem), "f"(lo_elem));
    return r;  // [15:0]=bf16(lo_elem), [31:16]=bf16(hi_elem)
}

#define LDSM_X4(r, addr) \
    asm volatile("ldmatrix.sync.aligned.m8n8.x4.shared.b16 {%0,%1,%2,%3}, [%4];" \
        : "=r"((r)[0]), "=r"((r)[1]), "=r"((r)[2]), "=r"((r)[3]) : "r"(addr))

#define LDSM_X4_T(r, addr) \
    asm volatile("ldmatrix.sync.aligned.m8n8.x4.trans.shared.b16 {%0,%1,%2,%3}, [%4];" \
        : "=r"((r)[0]), "=r"((r)[1]), "=r"((r)[2]), "=r"((r)[3]) : "r"(addr))

#define MMA_BF16(c, a, b0, b1) \
    asm volatile("mma.sync.aligned.m16n8k16.row.col.f32.bf16.bf16.f32 " \
        "{%0,%1,%2,%3}, {%4,%5,%6,%7}, {%8,%9}, {%0,%1,%2,%3};" \
        : "+f"((c)[0]), "+f"((c)[1]), "+f"((c)[2]), "+f"((c)[3]) \
        : "r"((a)[0]), "r"((a)[1]), "r"((a)[2]), "r"((a)[3]), "r"(b0), "r"(b1))

__device__ __forceinline__ void red_add_v4(float* dst, float a, float b, float c, float d) {
    asm volatile("red.global.add.v4.f32 [%0], {%1, %2, %3, %4};"
                 :: "l"(dst), "f"(a), "f"(b), "f"(c), "f"(d) : "memory");
}

__global__ void __launch_bounds__(THREADS, 2) sparse_conv_mma3(
    const float* __restrict__ x,
    const float* __restrict__ W,
    const int*   __restrict__ in_map,
    const int*   __restrict__ out_map,
    float*       __restrict__ out,
    int M, int T)          // T = total tiles = K * (M/128)
{
    extern __shared__ char smem[];
    const uint32_t sb = smem_u32(smem);
    int* idxs = (int*)(smem + SM_IDX);          // 3 slots x [in(128) | out(128)]
    const int tid  = threadIdx.x;
    const int w    = tid >> 5;
    const int lane = tid & 31;
    const int mg   = w >> 1;
    const int nh   = w & 1;
    const int ntk  = M >> 7;                    // tiles per k

    // fragment addressing
    const uint32_t b_off = (uint32_t)((lane & 15) * STRIDE_B + (lane >> 4) * 16 + nh * 64);
    const uint32_t a_off = (uint32_t)((32 * mg + (lane & 15)) * STRIDE_A + (lane >> 4) * 16);
    const bool odd = (lane & 1);
    const int  er0 = 32 * mg + (lane >> 2) + (odd ? 8 : 0);
    const int  q0  = (lane & 2) * 2;

    // balanced flattened range
    const int t_beg = (int)(((long long)blockIdx.x * T) / NCTAS);
    const int t_end = (int)(((long long)(blockIdx.x + 1) * T) / NCTAS);

    int t0 = t_beg;
    while (t0 < t_end) {
        const int k      = t0 / ntk;
        const int seg_end = min(t_end, (k + 1) * ntk);
        const int kM     = k * M;
        const int tl0    = t0 - k * ntk;        // local tile idx of segment start

        // --- stage W[k] -> bf16 hi/lo smem ---
        __syncthreads();
        {
            const float* Wk = W + (size_t)k * (CIN * COUT);
            #pragma unroll
            for (int i = 0; i < (CIN * COUT) / THREADS; i++) {
                const int lin = tid + i * THREADS;
                const int c = lin >> 6, n = lin & 63;
                const float wv = Wk[lin];
                const __nv_bfloat16 hv = __float2bfloat16(wv);
                const __nv_bfloat16 lv = __float2bfloat16(wv - __bfloat162float(hv));
                const uint32_t off = (uint32_t)(c * STRIDE_B + n * 2);
                *(__nv_bfloat16*)(smem + SM_B_HI + off) = hv;
                *(__nv_bfloat16*)(smem + SM_B_LO + off) = lv;
            }
        }
        // stage indices for first two tiles of segment
        {
            const int base0 = kM + (tl0 << 7);
            int* s0 = idxs + (t0 % 3) * 256;
            s0[tid] = (tid < 128) ? in_map[base0 + tid] : out_map[base0 + tid - 128];
            if (t0 + 1 < seg_end) {
                int* s1 = idxs + ((t0 + 1) % 3) * 256;
                const int base1 = base0 + 128;
                s1[tid] = (tid < 128) ? in_map[base1 + tid] : out_map[base1 + tid - 128];
            }
        }
        __syncthreads();

        // --- B-hi fragments to registers ---
        uint32_t bhr[4][2][4];
        #pragma unroll
        for (int s = 0; s < 4; s++)
            #pragma unroll
            for (int p = 0; p < 2; p++)
                LDSM_X4_T(bhr[s][p],
                          sb + SM_B_HI + b_off + (uint32_t)(s * 16 * STRIDE_B + p * 32));
        const uint32_t bLo = sb + SM_B_LO + b_off;

        // --- gather first tile into buf 0 ---
        {
            const int* inidx = idxs + (t0 % 3) * 256;
            char* hiA = smem;
            char* loA = smem + ABUF;
            #pragma unroll
            for (int j = 0; j < (EDGES * 16) / THREADS; j++) {
                const int f = tid + j * THREADS;
                const int e = f >> 4, q = f & 15;
                const int row = inidx[e];
                const float4 v = *(const float4*)(x + (size_t)row * CIN + q * 4);
                const uint32_t h0 = pack_bf16x2(v.y, v.x);
                const uint32_t h1 = pack_bf16x2(v.w, v.z);
                const float r0 = v.x - __uint_as_float(h0 << 16);
                const float r1 = v.y - __uint_as_float(h0 & 0xFFFF0000u);
                const float r2 = v.z - __uint_as_float(h1 << 16);
                const float r3 = v.w - __uint_as_float(h1 & 0xFFFF0000u);
                const uint32_t off = (uint32_t)(e * STRIDE_A + q * 8);
                *(uint2*)(hiA + off) = make_uint2(h0, h1);
                *(uint2*)(loA + off) = make_uint2(pack_bf16x2(r1, r0), pack_bf16x2(r3, r2));
            }
        }
        __syncthreads();

        int buf = 0;
        for (int t = t0; t < seg_end; t++, buf ^= 1) {
            // 1) epilogue out-rows for tile t -> regs
            const int* slot_t = idxs + (t % 3) * 256;
            const int orow0 = slot_t[128 + er0];
            const int orow1 = slot_t[128 + er0 + 16];

            // 2) stage indices for tile t+2
            if (t + 2 < seg_end) {
                int* sN = idxs + ((t + 2) % 3) * 256;
                const int baseN = kM + ((tl0 + (t + 2 - t0)) << 7);
                sN[tid] = (tid < 128) ? in_map[baseN + tid] : out_map[baseN + tid - 128];
            }

            // 3) gather tile t+1 into other buffer
            if (t + 1 < seg_end) {
                const int* inidx = idxs + ((t + 1) % 3) * 256;
                char* hiA = smem + (buf ^ 1) * (2 * ABUF);
                char* loA = hiA + ABUF;
                #pragma unroll
                for (int j = 0; j < (EDGES * 16) / THREADS; j++) {
                    const int f = tid + j * THREADS;
                    const int e = f >> 4, q = f & 15;
                    const int row = inidx[e];
                    const float4 v = *(const float4*)(x + (size_t)row * CIN + q * 4);
                    const uint32_t h0 = pack_bf16x2(v.y, v.x);
                    const uint32_t h1 = pack_bf16x2(v.w, v.z);
                    const float r0 = v.x - __uint_as_float(h0 << 16);
                    const float r1 = v.y - __uint_as_float(h0 & 0xFFFF0000u);
                    const float r2 = v.z - __uint_as_float(h1 << 16);
                    const float r3 = v.w - __uint_as_float(h1 & 0xFFFF0000u);
                    const uint32_t off = (uint32_t)(e * STRIDE_A + q * 8);
                    *(uint2*)(hiA + off) = make_uint2(h0, h1);
                    *(uint2*)(loA + off) = make_uint2(pack_bf16x2(r1, r0), pack_bf16x2(r3, r2));
                }
            }

            // 4) MMA on A[buf]: s -> (load 4 A frags) -> p -> (load bl once) -> 12 MMAs
            float acc[2][4][4];
            #pragma unroll
            for (int tt = 0; tt < 2; tt++)
                #pragma unroll
                for (int j = 0; j < 4; j++)
                    #pragma unroll
                    for (int i = 0; i < 4; i++) acc[tt][j][i] = 0.0f;

            const uint32_t aHi = sb + (uint32_t)(buf * 2 * ABUF) + a_off;
            const uint32_t aLo = aHi + ABUF;
            #pragma unroll
            for (int s = 0; s < 4; s++) {
                uint32_t ah0[4], al0[4], ah1[4], al1[4];
                LDSM_X4(ah0, aHi + (uint32_t)(s * 32));
                LDSM_X4(al0, aLo + (uint32_t)(s * 32));
                LDSM_X4(ah1, aHi + (uint32_t)(16 * STRIDE_A + s * 32));
                LDSM_X4(al1, aLo + (uint32_t)(16 * STRIDE_A + s * 32));
                #pragma unroll
                for (int p = 0; p < 2; p++) {
                    uint32_t bl[4];
                    LDSM_X4_T(bl, bLo + (uint32_t)(s * 16 * STRIDE_B + p * 32));
                    MMA_BF16(acc[0][2 * p],     ah0, bhr[s][p][0], bhr[s][p][1]);
                    MMA_BF16(acc[0][2 * p + 1], ah0, bhr[s][p][2], bhr[s][p][3]);
                    MMA_BF16(acc[0][2 * p],     ah0, bl[0], bl[1]);
                    MMA_BF16(acc[0][2 * p + 1], ah0, bl[2], bl[3]);
                    MMA_BF16(acc[0][2 * p],     al0, bhr[s][p][0], bhr[s][p][1]);
                    MMA_BF16(acc[0][2 * p + 1], al0, bhr[s][p][2], bhr[s][p][3]);
                    MMA_BF16(acc[1][2 * p],     ah1, bhr[s][p][0], bhr[s][p][1]);
                    MMA_BF16(acc[1][2 * p + 1], ah1, bhr[s][p][2], bhr[s][p][3]);
                    MMA_BF16(acc[1][2 * p],     ah1, bl[0], bl[1]);
                    MMA_BF16(acc[1][2 * p + 1], ah1, bl[2], bl[3]);
                    MMA_BF16(acc[1][2 * p],     al1, bhr[s][p][0], bhr[s][p][1]);
                    MMA_BF16(acc[1][2 * p + 1], al1, bhr[s][p][2], bhr[s][p][3]);
                }
            }

            // 5) epilogue: shfl pair-swap -> red.global.add.v4
            #pragma unroll
            for (int tt = 0; tt < 2; tt++) {
                const int orow = tt ? orow1 : orow0;
                float* obase = out + (size_t)orow * COUT + nh * 32 + q0;
                #pragma unroll
                for (int j = 0; j < 4; j++) {
                    float* c = acc[tt][j];
                    const float s0 = __shfl_xor_sync(0xFFFFFFFFu, c[0], 1);
                    const float s1 = __shfl_xor_sync(0xFFFFFFFFu, c[1], 1);
                    const float s2 = __shfl_xor_sync(0xFFFFFFFFu, c[2], 1);
                    const float s3 = __shfl_xor_sync(0xFFFFFFFFu, c[3], 1);
                    const float v0 = odd ? s2 : c[0];
                    const float v1 = odd ? s3 : c[1];
                    const float v2 = odd ? c[2] : s0;
                    const float v3 = odd ? c[3] : s1;
                    red_add_v4(obase + 8 * j, v0, v1, v2, v3);
                }
            }

            __syncthreads();
        }
        t0 = seg_end;
    }
}

extern "C" void kernel_launch(void* const* d_in, const int* in_sizes, int n_in,
                              void* d_out, int out_size)
{
    const float* x       = (const float*)d_in[0];
    const float* W       = (const float*)d_in[1];
    const int*   in_map  = (const int*)d_in[2];
    const int*   out_map = (const int*)d_in[3];
    float*       out     = (float*)d_out;

    const int K = in_sizes[1] / (CIN * COUT);   // 27
    const int M = in_sizes[2] / K;              // 65536
    const int T = K * (M >> 7);                 // 13824 tiles

    static bool attr_set = false;
    if (!attr_set) {
        cudaFuncSetAttribute(sparse_conv_mma3,
                             cudaFuncAttributeMaxDynamicSharedMemorySize, SM_TOTAL);
        attr_set = true;
    }

    cudaMemsetAsync(d_out, 0, (size_t)out_size * sizeof(float), 0);

    sparse_conv_mma3<<<NCTAS, THREADS, SM_TOTAL>>>(x, W, in_map, out_map, out, M, T);
}

// round 7
// speedup vs baseline: 1.2766x; 1.2766x over previous
#include <cuda_runtime.h>
#include <cuda_bf16.h>
#include <cstddef>
#include <cstdint>

// SparseConv: out[out_map[k,m]] += x[in_map[k,m]] @ W[k]   (K=27, M=65536, Cin=Cout=64)
//
// Round 7: R5 skeleton (known-good 251.9us) + ONE change:
//   MMA loop reordered s-outer so B-lo fragments load once per s (8 vs 16 LDSM_T/tile),
//   with bounded live-set (~120 regs, no spill).
//   - B-hi fragments in registers (loaded once per CTA; warp = 32 rows x 32 cols)
//   - double-buffered A + software-pipelined gather (1 sync per tile)
//   - grid (10, 27): 270 CTAs, 2/SM

#define CIN     64
#define COUT    64
#define EDGES   128
#define THREADS 256
#define CTAS_X  10

#define STRIDE_A 144
#define STRIDE_B 144

#define ABUF     (EDGES * STRIDE_A)        // 18432 bytes per (buf, hi/lo) plane
#define SM_B_HI  (4 * ABUF)                // 73728
#define SM_B_LO  (SM_B_HI + CIN * STRIDE_B)
#define SM_TOTAL (SM_B_LO + CIN * STRIDE_B)  // 92160 bytes -> 2 CTAs/SM

__device__ __forceinline__ uint32_t smem_u32(const void* p) {
    uint32_t a;
    asm("{ .reg .u64 t; cvta.to.shared.u64 t, %1; cvt.u32.u64 %0, t; }" : "=r"(a) : "l"(p));
    return a;
}
__device__ __forceinline__ uint32_t pack_bf16x2(float hi_elem, float lo_elem) {
    uint32_t r;
    asm("cvt.rn.bf16x2.f32 %0, %1, %2;" : "=r"(r) : "f"(hi_elem), "f"(lo_elem));
    return r;  // [15:0]=bf16(lo_elem), [31:16]=bf16(hi_elem)
}

#define LDSM_X4(r, addr) \
    asm volatile("ldmatrix.sync.aligned.m8n8.x4.shared.b16 {%0,%1,%2,%3}, [%4];" \
        : "=r"((r)[0]), "=r"((r)[1]), "=r"((r)[2]), "=r"((r)[3]) : "r"(addr))

#define LDSM_X4_T(r, addr) \
    asm volatile("ldmatrix.sync.aligned.m8n8.x4.trans.shared.b16 {%0,%1,%2,%3}, [%4];" \
        : "=r"((r)[0]), "=r"((r)[1]), "=r"((r)[2]), "=r"((r)[3]) : "r"(addr))

#define MMA_BF16(c, a, b0, b1) \
    asm volatile("mma.sync.aligned.m16n8k16.row.col.f32.bf16.bf16.f32 " \
        "{%0,%1,%2,%3}, {%4,%5,%6,%7}, {%8,%9}, {%0,%1,%2,%3};" \
        : "+f"((c)[0]), "+f"((c)[1]), "+f"((c)[2]), "+f"((c)[3]) \
        : "r"((a)[0]), "r"((a)[1]), "r"((a)[2]), "r"((a)[3]), "r"(b0), "r"(b1))

__device__ __forceinline__ void red_add_v4(float* dst, float a, float b, float c, float d) {
    asm volatile("red.global.add.v4.f32 [%0], {%1, %2, %3, %4};"
                 :: "l"(dst), "f"(a), "f"(b), "f"(c), "f"(d) : "memory");
}

// gather 128 x-rows of tile, split fp32 -> bf16 hi/lo, into buffer b
__device__ __forceinline__ void gather_tile(
    char* smem, int b, const float* __restrict__ x,
    const int* __restrict__ in_map, int kMm0, int tid)
{
    char* hiA = smem + b * (2 * ABUF);
    char* loA = hiA + ABUF;
    #pragma unroll
    for (int j = 0; j < (EDGES * 16) / THREADS; j++) {
        const int f = tid + j * THREADS;
        const int e = f >> 4;
        const int q = f & 15;
        const int row = in_map[kMm0 + e];
        const float4 v = *(const float4*)(x + (size_t)row * CIN + q * 4);
        const uint32_t h0 = pack_bf16x2(v.y, v.x);
        const uint32_t h1 = pack_bf16x2(v.w, v.z);
        const float r0 = v.x - __uint_as_float(h0 << 16);
        const float r1 = v.y - __uint_as_float(h0 & 0xFFFF0000u);
        const float r2 = v.z - __uint_as_float(h1 << 16);
        const float r3 = v.w - __uint_as_float(h1 & 0xFFFF0000u);
        const uint32_t l0 = pack_bf16x2(r1, r0);
        const uint32_t l1 = pack_bf16x2(r3, r2);
        const uint32_t off = (uint32_t)(e * STRIDE_A + q * 8);
        *(uint2*)(hiA + off) = make_uint2(h0, h1);
        *(uint2*)(loA + off) = make_uint2(l0, l1);
    }
}

__global__ void __launch_bounds__(THREADS, 2) sparse_conv_mma4(
    const float* __restrict__ x,
    const float* __restrict__ W,
    const int*   __restrict__ in_map,
    const int*   __restrict__ out_map,
    float*       __restrict__ out,
    int M)
{
    extern __shared__ char smem[];
    const uint32_t sb = smem_u32(smem);
    const int tid  = threadIdx.x;
    const int w    = tid >> 5;
    const int lane = tid & 31;
    const int mg   = w >> 1;        // rows 32*mg .. 32*mg+31
    const int nh   = w & 1;         // cols 32*nh .. 32*nh+31
    const int k    = blockIdx.y;
    const int kM   = k * M;
    const int ntiles = M >> 7;

    // --- stage W[k] -> bf16 hi/lo in smem ---
    {
        const float* Wk = W + (size_t)k * (CIN * COUT);
        #pragma unroll
        for (int i = 0; i < (CIN * COUT) / THREADS; i++) {
            const int lin = tid + i * THREADS;
            const int c = lin >> 6, n = lin & 63;
            const float wv = Wk[lin];
            const __nv_bfloat16 hv = __float2bfloat16(wv);
            const __nv_bfloat16 lv = __float2bfloat16(wv - __bfloat162float(hv));
            const uint32_t off = (uint32_t)(c * STRIDE_B + n * 2);
            *(__nv_bfloat16*)(smem + SM_B_HI + off) = hv;
            *(__nv_bfloat16*)(smem + SM_B_LO + off) = lv;
        }
    }
    __syncthreads();

    // --- B-hi fragments for this warp's 32 cols -> registers ---
    const uint32_t b_off = (uint32_t)((lane & 15) * STRIDE_B + (lane >> 4) * 16 + nh * 64);
    uint32_t bhr[4][2][4];
    #pragma unroll
    for (int s = 0; s < 4; s++)
        #pragma unroll
        for (int p = 0; p < 2; p++)
            LDSM_X4_T(bhr[s][p], sb + SM_B_HI + b_off + (uint32_t)(s * 16 * STRIDE_B + p * 32));
    const uint32_t bLo = sb + SM_B_LO + b_off;

    const uint32_t a_off = (uint32_t)((32 * mg + (lane & 15)) * STRIDE_A + (lane >> 4) * 16);

    // epilogue lane mapping
    const bool odd = (lane & 1);
    const int  er0 = 32 * mg + (lane >> 2) + (odd ? 8 : 0);
    const int  q0  = (lane & 2) * 2;

    int mt = blockIdx.x;
    gather_tile(smem, 0, x, in_map, kM + (mt << 7), tid);
    __syncthreads();
    int buf = 0;

    while (mt < ntiles) {
        const int nxt = mt + CTAS_X;
        // pipelined gather of next tile into other buffer
        if (nxt < ntiles)
            gather_tile(smem, buf ^ 1, x, in_map, kM + (nxt << 7), tid);

        // --- MMA: s-outer; B-lo loaded once per s (both p), t inner ---
        float acc[2][4][4];
        #pragma unroll
        for (int t = 0; t < 2; t++)
            #pragma unroll
            for (int j = 0; j < 4; j++)
                #pragma unroll
                for (int i = 0; i < 4; i++) acc[t][j][i] = 0.0f;

        const uint32_t aHi = sb + (uint32_t)(buf * 2 * ABUF) + a_off;
        const uint32_t aLo = aHi + ABUF;
        #pragma unroll
        for (int s = 0; s < 4; s++) {
            uint32_t bl[2][4];
            LDSM_X4_T(bl[0], bLo + (uint32_t)(s * 16 * STRIDE_B));
            LDSM_X4_T(bl[1], bLo + (uint32_t)(s * 16 * STRIDE_B + 32));
            #pragma unroll
            for (int t = 0; t < 2; t++) {
                uint32_t ah[4], al[4];
                const uint32_t ao = (uint32_t)(t * 16 * STRIDE_A + s * 32);
                LDSM_X4(ah, aHi + ao);
                LDSM_X4(al, aLo + ao);
                #pragma unroll
                for (int p = 0; p < 2; p++) {
                    MMA_BF16(acc[t][2 * p],     ah, bhr[s][p][0], bhr[s][p][1]);
                    MMA_BF16(acc[t][2 * p + 1], ah, bhr[s][p][2], bhr[s][p][3]);
                    MMA_BF16(acc[t][2 * p],     ah, bl[p][0], bl[p][1]);
                    MMA_BF16(acc[t][2 * p + 1], ah, bl[p][2], bl[p][3]);
                    MMA_BF16(acc[t][2 * p],     al, bhr[s][p][0], bhr[s][p][1]);
                    MMA_BF16(acc[t][2 * p + 1], al, bhr[s][p][2], bhr[s][p][3]);
                }
            }
        }

        // --- epilogue: shfl pair-swap -> red.global.add.v4 ---
        {
            const int m0 = mt << 7;
            #pragma unroll
            for (int t = 0; t < 2; t++) {
                const int orow = out_map[kM + m0 + er0 + t * 16];
                float* obase = out + (size_t)orow * COUT + nh * 32 + q0;
                #pragma unroll
                for (int j = 0; j < 4; j++) {
                    float* c = acc[t][j];
                    const float s0 = __shfl_xor_sync(0xFFFFFFFFu, c[0], 1);
                    const float s1 = __shfl_xor_sync(0xFFFFFFFFu, c[1], 1);
                    const float s2 = __shfl_xor_sync(0xFFFFFFFFu, c[2], 1);
                    const float s3 = __shfl_xor_sync(0xFFFFFFFFu, c[3], 1);
                    const float v0 = odd ? s2 : c[0];
                    const float v1 = odd ? s3 : c[1];
                    const float v2 = odd ? c[2] : s0;
                    const float v3 = odd ? c[3] : s1;
                    red_add_v4(obase + 8 * j, v0, v1, v2, v3);
                }
            }
        }
        __syncthreads();
        mt = nxt;
        buf ^= 1;
    }
}

extern "C" void kernel_launch(void* const* d_in, const int* in_sizes, int n_in,
                              void* d_out, int out_size)
{
    const float* x       = (const float*)d_in[0];
    const float* W       = (const float*)d_in[1];
    const int*   in_map  = (const int*)d_in[2];
    const int*   out_map = (const int*)d_in[3];
    float*       out     = (float*)d_out;

    const int K = in_sizes[1] / (CIN * COUT);   // 27
    const int M = in_sizes[2] / K;              // 65536

    static bool attr_set = false;
    if (!attr_set) {
        cudaFuncSetAttribute(sparse_conv_mma4,
                             cudaFuncAttributeMaxDynamicSharedMemorySize, SM_TOTAL);
        attr_set = true;
    }

    cudaMemsetAsync(d_out, 0, (size_t)out_size * sizeof(float), 0);

    dim3 grid(CTAS_X, K);
    sparse_conv_mma4<<<grid, THREADS, SM_TOTAL>>>(x, W, in_map, out_map, out, M);
}

// round 8
// speedup vs baseline: 1.4041x; 1.0999x over previous
#include <cuda_runtime.h>
#include <cuda_bf16.h>
#include <cstddef>
#include <cstdint>

// SparseConv: out[out_map[k,m]] += x[in_map[k,m]] @ W[k]   (K=27, M=65536, Cin=Cout=64)
//
// Round 8: occupancy play. All B fragments from smem (no reg hoist), single A buffer,
// __launch_bounds__(256,3) -> ~85 regs -> 3 CTAs/SM (24 warps). Cross-CTA overlap
// replaces intra-CTA double buffering. Grid (16,27)=432 CTAs, 32 tiles each.

#define CIN     64
#define COUT    64
#define EDGES   128
#define THREADS 256
#define CTAS_X  16

#define STRIDE_A 144
#define STRIDE_B 144

#define ABUF     (EDGES * STRIDE_A)          // 18432 B per hi/lo plane
#define SM_A_HI  0
#define SM_A_LO  ABUF                        // 18432
#define SM_B_HI  (2 * ABUF)                  // 36864
#define SM_B_LO  (SM_B_HI + CIN * STRIDE_B)  // 46080
#define SM_TOTAL (SM_B_LO + CIN * STRIDE_B)  // 55296 B -> 3 CTAs/SM (smem), 3 by regs

__device__ __forceinline__ uint32_t smem_u32(const void* p) {
    uint32_t a;
    asm("{ .reg .u64 t; cvta.to.shared.u64 t, %1; cvt.u32.u64 %0, t; }" : "=r"(a) : "l"(p));
    return a;
}
__device__ __forceinline__ uint32_t pack_bf16x2(float hi_elem, float lo_elem) {
    uint32_t r;
    asm("cvt.rn.bf16x2.f32 %0, %1, %2;" : "=r"(r) : "f"(hi_elem), "f"(lo_elem));
    return r;  // [15:0]=bf16(lo_elem), [31:16]=bf16(hi_elem)
}

#define LDSM_X4(r, addr) \
    asm volatile("ldmatrix.sync.aligned.m8n8.x4.shared.b16 {%0,%1,%2,%3}, [%4];" \
        : "=r"((r)[0]), "=r"((r)[1]), "=r"((r)[2]), "=r"((r)[3]) : "r"(addr))

#define LDSM_X4_T(r, addr) \
    asm volatile("ldmatrix.sync.aligned.m8n8.x4.trans.shared.b16 {%0,%1,%2,%3}, [%4];" \
        : "=r"((r)[0]), "=r"((r)[1]), "=r"((r)[2]), "=r"((r)[3]) : "r"(addr))

#define MMA_BF16(c, a, b0, b1) \
    asm volatile("mma.sync.aligned.m16n8k16.row.col.f32.bf16.bf16.f32 " \
        "{%0,%1,%2,%3}, {%4,%5,%6,%7}, {%8,%9}, {%0,%1,%2,%3};" \
        : "+f"((c)[0]), "+f"((c)[1]), "+f"((c)[2]), "+f"((c)[3]) \
        : "r"((a)[0]), "r"((a)[1]), "r"((a)[2]), "r"((a)[3]), "r"(b0), "r"(b1))

__device__ __forceinline__ void red_add_v4(float* dst, float a, float b, float c, float d) {
    asm volatile("red.global.add.v4.f32 [%0], {%1, %2, %3, %4};"
                 :: "l"(dst), "f"(a), "f"(b), "f"(c), "f"(d) : "memory");
}

__global__ void __launch_bounds__(THREADS, 3) sparse_conv_mma5(
    const float* __restrict__ x,
    const float* __restrict__ W,
    const int*   __restrict__ in_map,
    const int*   __restrict__ out_map,
    float*       __restrict__ out,
    int M)
{
    extern __shared__ char smem[];
    const uint32_t sb = smem_u32(smem);
    const int tid  = threadIdx.x;
    const int w    = tid >> 5;
    const int lane = tid & 31;
    const int mg   = w >> 1;        // rows 32*mg .. 32*mg+31
    const int nh   = w & 1;         // cols 32*nh .. 32*nh+31
    const int k    = blockIdx.y;
    const int kM   = k * M;
    const int ntiles = M >> 7;

    // --- stage W[k] -> bf16 hi/lo in smem ---
    {
        const float* Wk = W + (size_t)k * (CIN * COUT);
        #pragma unroll
        for (int i = 0; i < (CIN * COUT) / THREADS; i++) {
            const int lin = tid + i * THREADS;
            const int c = lin >> 6, n = lin & 63;
            const float wv = Wk[lin];
            const __nv_bfloat16 hv = __float2bfloat16(wv);
            const __nv_bfloat16 lv = __float2bfloat16(wv - __bfloat162float(hv));
            const uint32_t off = (uint32_t)(c * STRIDE_B + n * 2);
            *(__nv_bfloat16*)(smem + SM_B_HI + off) = hv;
            *(__nv_bfloat16*)(smem + SM_B_LO + off) = lv;
        }
    }

    // fragment addressing
    const uint32_t b_off = (uint32_t)((lane & 15) * STRIDE_B + (lane >> 4) * 16 + nh * 64);
    const uint32_t bHi = sb + SM_B_HI + b_off;
    const uint32_t bLo = sb + SM_B_LO + b_off;
    const uint32_t a_off = (uint32_t)((32 * mg + (lane & 15)) * STRIDE_A + (lane >> 4) * 16);
    const uint32_t aHi = sb + SM_A_HI + a_off;
    const uint32_t aLo = sb + SM_A_LO + a_off;

    // epilogue lane mapping
    const bool odd = (lane & 1);
    const int  er0 = 32 * mg + (lane >> 2) + (odd ? 8 : 0);
    const int  q0  = (lane & 2) * 2;

    for (int mt = blockIdx.x; mt < ntiles; mt += CTAS_X) {
        const int m0 = mt << 7;

        __syncthreads();   // previous tile's LDSM readers done before overwrite

        // --- gather 128 x-rows, split fp32 -> bf16 hi/lo ---
        #pragma unroll
        for (int j = 0; j < (EDGES * 16) / THREADS; j++) {
            const int f = tid + j * THREADS;
            const int e = f >> 4, q = f & 15;
            const int row = in_map[kM + m0 + e];
            const float4 v = *(const float4*)(x + (size_t)row * CIN + q * 4);
            const uint32_t h0 = pack_bf16x2(v.y, v.x);
            const uint32_t h1 = pack_bf16x2(v.w, v.z);
            const float r0 = v.x - __uint_as_float(h0 << 16);
            const float r1 = v.y - __uint_as_float(h0 & 0xFFFF0000u);
            const float r2 = v.z - __uint_as_float(h1 << 16);
            const float r3 = v.w - __uint_as_float(h1 & 0xFFFF0000u);
            const uint32_t off = (uint32_t)(e * STRIDE_A + q * 8);
            *(uint2*)(smem + SM_A_HI + off) = make_uint2(h0, h1);
            *(uint2*)(smem + SM_A_LO + off) = make_uint2(pack_bf16x2(r1, r0), pack_bf16x2(r3, r2));
        }

        // prefetch epilogue rows (off the RED critical path)
        const int orow0 = out_map[kM + m0 + er0];
        const int orow1 = out_map[kM + m0 + er0 + 16];

        __syncthreads();

        // --- MMA: s-outer; B hi+lo from smem once per s; t inner ---
        float acc[2][4][4];
        #pragma unroll
        for (int t = 0; t < 2; t++)
            #pragma unroll
            for (int j = 0; j < 4; j++)
                #pragma unroll
                for (int i = 0; i < 4; i++) acc[t][j][i] = 0.0f;

        #pragma unroll
        for (int s = 0; s < 4; s++) {
            uint32_t bh[2][4], bl[2][4];
            const uint32_t so = (uint32_t)(s * 16 * STRIDE_B);
            LDSM_X4_T(bh[0], bHi + so);
            LDSM_X4_T(bh[1], bHi + so + 32);
            LDSM_X4_T(bl[0], bLo + so);
            LDSM_X4_T(bl[1], bLo + so + 32);
            #pragma unroll
            for (int t = 0; t < 2; t++) {
                uint32_t ah[4], al[4];
                const uint32_t ao = (uint32_t)(t * 16 * STRIDE_A + s * 32);
                LDSM_X4(ah, aHi + ao);
                LDSM_X4(al, aLo + ao);
                #pragma unroll
                for (int p = 0; p < 2; p++) {
                    MMA_BF16(acc[t][2 * p],     ah, bh[p][0], bh[p][1]);
                    MMA_BF16(acc[t][2 * p + 1], ah, bh[p][2], bh[p][3]);
                    MMA_BF16(acc[t][2 * p],     ah, bl[p][0], bl[p][1]);
                    MMA_BF16(acc[t][2 * p + 1], ah, bl[p][2], bl[p][3]);
                    MMA_BF16(acc[t][2 * p],     al, bh[p][0], bh[p][1]);
                    MMA_BF16(acc[t][2 * p + 1], al, bh[p][2], bh[p][3]);
                }
            }
        }

        // --- epilogue: shfl pair-swap -> red.global.add.v4 ---
        #pragma unroll
        for (int t = 0; t < 2; t++) {
            const int orow = t ? orow1 : orow0;
            float* obase = out + (size_t)orow * COUT + nh * 32 + q0;
            #pragma unroll
            for (int j = 0; j < 4; j++) {
                float* c = acc[t][j];
                const float s0 = __shfl_xor_sync(0xFFFFFFFFu, c[0], 1);
                const float s1 = __shfl_xor_sync(0xFFFFFFFFu, c[1], 1);
                const float s2 = __shfl_xor_sync(0xFFFFFFFFu, c[2], 1);
                const float s3 = __shfl_xor_sync(0xFFFFFFFFu, c[3], 1);
                const float v0 = odd ? s2 : c[0];
                const float v1 = odd ? s3 : c[1];
                const float v2 = odd ? c[2] : s0;
                const float v3 = odd ? c[3] : s1;
                red_add_v4(obase + 8 * j, v0, v1, v2, v3);
            }
        }
    }
}

extern "C" void kernel_launch(void* const* d_in, const int* in_sizes, int n_in,
                              void* d_out, int out_size)
{
    const float* x       = (const float*)d_in[0];
    const float* W       = (const float*)d_in[1];
    const int*   in_map  = (const int*)d_in[2];
    const int*   out_map = (const int*)d_in[3];
    float*       out     = (float*)d_out;

    const int K = in_sizes[1] / (CIN * COUT);   // 27
    const int M = in_sizes[2] / K;              // 65536

    static bool attr_set = false;
    if (!attr_set) {
        cudaFuncSetAttribute(sparse_conv_mma5,
                             cudaFuncAttributeMaxDynamicSharedMemorySize, SM_TOTAL);
        attr_set = true;
    }

    cudaMemsetAsync(d_out, 0, (size_t)out_size * sizeof(float), 0);

    dim3 grid(CTAS_X, K);
    sparse_conv_mma5<<<grid, THREADS, SM_TOTAL>>>(x, W, in_map, out_map, out, M);
}